// round 4
// baseline (speedup 1.0000x reference)
#include <cuda_runtime.h>
#include <cstdint>

// CRF NLL:  out[b] = logZ[b] - score_sentence[b]
// B=512, S=1024, T=48. Forward scan in linear domain:
//   p_k = (E @ p_{k-1}) .* exp(emit_k),  E = exp(trans)
// Two warps per batch: warp w owns rows [24w,24w+24), one row per lane
// (E row = 24 packed f32x2 regs). p exchanged via smem double buffer +
// one __syncthreads per step. Renormalized once per 4-step group by p[0]
// (scale folded into the pre-exponentiated emission ring, off-path);
// log2 scales Kahan-accumulated in fp32.

static constexpr int T_ = 48;
static constexpr int S_ = 1024;
static constexpr int START_ = 45;
static constexpr int STOP_ = 46;
static constexpr float LOG2E_ = 1.4426950408889634f;
static constexpr float LN2_ = 0.6931471805599453f;

__device__ int g_len[2048];

__device__ __forceinline__ float ex2f_(float x) {
    float y; asm("ex2.approx.ftz.f32 %0, %1;" : "=f"(y) : "f"(x)); return y;
}
__device__ __forceinline__ float lg2f_(float x) {
    float y; asm("lg2.approx.f32 %0, %1;" : "=f"(y) : "f"(x)); return y;
}
__device__ __forceinline__ unsigned long long pack2_(float lo, float hi) {
    unsigned long long r; asm("mov.b64 %0, {%1,%2};" : "=l"(r) : "f"(lo), "f"(hi)); return r;
}
__device__ __forceinline__ void fma2_(unsigned long long& acc, unsigned long long a, unsigned long long b) {
    asm("fma.rn.f32x2 %0, %1, %2, %0;" : "+l"(acc) : "l"(a), "l"(b));
}
__device__ __forceinline__ unsigned long long add2_(unsigned long long a, unsigned long long b) {
    unsigned long long r; asm("add.rn.f32x2 %0, %1, %2;" : "=l"(r) : "l"(a), "l"(b)); return r;
}
__device__ __forceinline__ void unpack2_(unsigned long long v, float& lo, float& hi) {
    asm("mov.b64 {%0,%1}, %2;" : "=f"(lo), "=f"(hi) : "l"(v));
}

// ---------------------------------------------------------------------------
// Kernel 1: score_sentence per batch + sequence length.
// ---------------------------------------------------------------------------
__global__ void score_sent_kernel(const float* __restrict__ feats,
                                  const float* __restrict__ masks,
                                  const int* __restrict__ tags,
                                  const float* __restrict__ trans,
                                  float* __restrict__ out) {
    __shared__ float st[T_ * T_];
    __shared__ float rs[8];
    __shared__ int   rc[8];

    const int b   = blockIdx.x;
    const int tid = threadIdx.x;

    for (int i = tid; i < T_ * T_; i += blockDim.x) st[i] = trans[i];
    __syncthreads();

    const float* mrow = masks + (size_t)b * S_;
    const int*   trow = tags  + (size_t)b * S_;
    const float* frow = feats + (size_t)b * S_ * T_;

    float sum = 0.0f;
    int   cnt = 0;
    for (int s = tid; s < S_; s += blockDim.x) {
        if (mrow[s] != 0.0f) {
            cnt++;
            int tg = trow[s];
            int tp = (s == 0) ? START_ : trow[s - 1];
            sum += frow[s * T_ + tg] + st[tg * T_ + tp];
        }
    }
    #pragma unroll
    for (int o = 16; o > 0; o >>= 1) {
        sum += __shfl_xor_sync(0xffffffffu, sum, o);
        cnt += __shfl_xor_sync(0xffffffffu, cnt, o);
    }
    const int w = tid >> 5;
    if ((tid & 31) == 0) { rs[w] = sum; rc[w] = cnt; }
    __syncthreads();
    if (tid == 0) {
        float tot = 0.0f;
        int   len = 0;
        const int nw = blockDim.x >> 5;
        for (int i = 0; i < nw; i++) { tot += rs[i]; len += rc[i]; }
        int last = trow[len - 1];
        tot += st[STOP_ * T_ + last];
        out[b]   = tot;
        g_len[b] = len;
    }
}

// ---------------------------------------------------------------------------
// Kernel 2: forward scan, 2 warps per batch (64-thread blocks).
// ---------------------------------------------------------------------------
__global__ void __launch_bounds__(64, 8)
crf_scan_kernel(const float* __restrict__ feats,
                const float* __restrict__ trans,
                float* __restrict__ out) {
    __shared__ float4 pbuf4[2][12];              // double-buffered p (48 floats)
    __shared__ float  wpart[2];

    const int b    = blockIdx.x;
    const int tid  = threadIdx.x;
    const int warp = tid >> 5;
    const int lane = tid & 31;

    const int  t      = warp * 24 + lane;        // owned row
    const bool active = (lane < 24);
    const int  t_ld   = active ? t : 0;          // clamped (safe, branch-free)

    const float* f = feats + (size_t)b * S_ * T_;
    const int len   = g_len[b];
    const int lenm1 = len - 1;

    // --- Prologue: my E row (24 packed f32x2); NEG -> exact 0 ---
    unsigned long long er[24];
    #pragma unroll
    for (int j = 0; j < 24; j++) {
        float a = 0.0f, c = 0.0f;
        if (active) {
            a = expf(trans[t * T_ + 2 * j]);
            c = expf(trans[t * T_ + 2 * j + 1]);
        }
        er[j] = pack2_(a, c);
    }
    const float esr = active ? expf(trans[STOP_ * T_ + t]) : 0.0f;

    // --- init p0 = delta(START) ---
    {
        float* p0 = reinterpret_cast<float*>(&pbuf4[0][0]);
        if (tid < T_) p0[tid] = (tid == START_) ? 1.0f : 0.0f;
    }

    // --- emission pipeline: eE[] for group 0 (exp'd); emn[] raw*log2e for g1 ---
    float eE[4], emn[4];
    #pragma unroll
    for (int j = 0; j < 4; j++) {
        int k1 = (j     <= lenm1) ? j     : lenm1;
        int k2 = (j + 4 <= lenm1) ? j + 4 : lenm1;
        eE[j]  = ex2f_(f[k1 * T_ + t_ld] * LOG2E_);
        emn[j] = f[k2 * T_ + t_ld] * LOG2E_;
    }

    float Asum = 0.0f, Acmp = 0.0f;              // Kahan log2-normalizer
    float pend = 0.0f;                           // scale applied in eE[0], to add
    float r = 0.0f;
    unsigned long long vlast = 0ull;             // v0.x captured each step

    __syncthreads();

    const int nfull = len >> 2;
    const int rem   = len & 3;

#define STEPG(J, EEV)                                                         \
    {                                                                         \
        const ulonglong2* pv =                                                \
            reinterpret_cast<const ulonglong2*>(&pbuf4[(J) & 1][0]);          \
        ulonglong2 v0 = pv[0], v1 = pv[1], v2 = pv[2];                        \
        ulonglong2 v3 = pv[3], v4 = pv[4], v5 = pv[5];                        \
        ulonglong2 v6 = pv[6], v7 = pv[7], v8 = pv[8];                        \
        ulonglong2 v9 = pv[9], v10 = pv[10], v11 = pv[11];                    \
        vlast = v0.x;                                                         \
        unsigned long long q0 = 0ull, q1 = 0ull, q2 = 0ull, q3 = 0ull;        \
        fma2_(q0, er[0],  v0.x);  fma2_(q1, er[6],  v3.x);                    \
        fma2_(q2, er[12], v6.x);  fma2_(q3, er[18], v9.x);                    \
        fma2_(q0, er[1],  v0.y);  fma2_(q1, er[7],  v3.y);                    \
        fma2_(q2, er[13], v6.y);  fma2_(q3, er[19], v9.y);                    \
        fma2_(q0, er[2],  v1.x);  fma2_(q1, er[8],  v4.x);                    \
        fma2_(q2, er[14], v7.x);  fma2_(q3, er[20], v10.x);                   \
        fma2_(q0, er[3],  v1.y);  fma2_(q1, er[9],  v4.y);                    \
        fma2_(q2, er[15], v7.y);  fma2_(q3, er[21], v10.y);                   \
        fma2_(q0, er[4],  v2.x);  fma2_(q1, er[10], v5.x);                    \
        fma2_(q2, er[16], v8.x);  fma2_(q3, er[22], v11.x);                   \
        fma2_(q0, er[5],  v2.y);  fma2_(q1, er[11], v5.y);                    \
        fma2_(q2, er[17], v8.y);  fma2_(q3, er[23], v11.y);                   \
        unsigned long long s = add2_(add2_(q0, q1), add2_(q2, q3));           \
        float dl, dh;                                                         \
        unpack2_(s, dl, dh);                                                  \
        r = (dl + dh) * (EEV);                                                \
        float* pn = reinterpret_cast<float*>(&pbuf4[((J) & 1) ^ 1][0]);       \
        if (active) pn[t] = r;                                                \
        __syncthreads();                                                      \
    }

    for (int g = 0; g < nfull; g++) {
        // Kahan-accumulate the scale applied in this group's eE[0]
        {
            float y  = pend - Acmp;
            float tt = Asum + y;
            Acmp = (tt - Asum) - y;
            Asum = tt;
        }
        // prefetch raw emissions for group g+2 (clamped, branch-free, MLP=4)
        const int kb = g * 4 + 8;
        const int a0 = (kb     <= lenm1) ? kb     : lenm1;
        const int a1 = (kb + 1 <= lenm1) ? kb + 1 : lenm1;
        const int a2 = (kb + 2 <= lenm1) ? kb + 2 : lenm1;
        const int a3 = (kb + 3 <= lenm1) ? kb + 3 : lenm1;
        const float l0 = f[(size_t)a0 * T_ + t_ld];
        const float l1 = f[(size_t)a1 * T_ + t_ld];
        const float l2 = f[(size_t)a2 * T_ + t_ld];
        const float l3 = f[(size_t)a3 * T_ + t_ld];

        STEPG(0, eE[0])
        STEPG(1, eE[1])
        STEPG(2, eE[2])
        STEPG(3, eE[3])

        // group epilogue (off critical path): measure renorm from p[0] seen at
        // step 3; build next group's eE ring with scale folded into eE[0]
        {
            float p0l, p0h;
            unpack2_(vlast, p0l, p0h);
            const float m  = lg2f_(p0l);
            const float sc = ex2f_(-m);
            pend = m;
            eE[0] = ex2f_(emn[0]) * sc;
            eE[1] = ex2f_(emn[1]);
            eE[2] = ex2f_(emn[2]);
            eE[3] = ex2f_(emn[3]);
            emn[0] = l0 * LOG2E_;
            emn[1] = l1 * LOG2E_;
            emn[2] = l2 * LOG2E_;
            emn[3] = l3 * LOG2E_;
        }
    }
#undef STEPG

    // --- remainder (0..3 steps, dynamic parity) ---
    for (int j = 0; j < rem; j++) {
        const ulonglong2* pv =
            reinterpret_cast<const ulonglong2*>(&pbuf4[j & 1][0]);
        unsigned long long q0 = 0ull, q1 = 0ull;
        #pragma unroll
        for (int i = 0; i < 6; i++) {
            ulonglong2 a = pv[i], c = pv[i + 6];
            fma2_(q0, er[2 * i],      a.x);
            fma2_(q0, er[2 * i + 1],  a.y);
            fma2_(q1, er[12 + 2 * i], c.x);
            fma2_(q1, er[13 + 2 * i], c.y);
        }
        unsigned long long s = add2_(q0, q1);
        float dl, dh;
        unpack2_(s, dl, dh);
        r = (dl + dh) * eE[j];
        if (j == 0) {                 // scale from last group folded into eE[0]
            float y  = pend - Acmp;
            float tt = Asum + y;
            Acmp = (tt - Asum) - y;
            Asum = tt;
        }
        float* pn = reinterpret_cast<float*>(&pbuf4[(j & 1) ^ 1][0]);
        if (active) pn[t] = r;
        __syncthreads();
    }

    // --- final: logZ = ln2 * (Asum + log2( sum_t p_L[t] * E_stop[t] )) ---
    float part = active ? r * esr : 0.0f;
    #pragma unroll
    for (int o = 16; o > 0; o >>= 1) part += __shfl_xor_sync(0xffffffffu, part, o);
    if (lane == 0) wpart[warp] = part;
    __syncthreads();
    if (tid == 0) {
        float tot  = wpart[0] + wpart[1];
        float logZ = (Asum + lg2f_(tot)) * LN2_;
        out[b] = logZ - out[b];
    }
}

// ---------------------------------------------------------------------------
extern "C" void kernel_launch(void* const* d_in, const int* in_sizes, int n_in,
                              void* d_out, int out_size) {
    const float* feats = (const float*)d_in[0];
    const float* masks = (const float*)d_in[1];
    const int*   tags  = (const int*)d_in[2];
    const float* trans = (const float*)d_in[3];
    float* out = (float*)d_out;
    const int B = out_size;                 // 512

    score_sent_kernel<<<B, 256>>>(feats, masks, tags, trans, out);
    crf_scan_kernel<<<B, 64>>>(feats, trans, out);
}